// round 6
// baseline (speedup 1.0000x reference)
#include <cuda_runtime.h>
#include <cuda_bf16.h>
#include <math.h>

#define KBINS 5
#define TAILB 2.5f
#define TPB 256
#define VPT 2   // float4 per thread

__device__ __forceinline__ float rcp_approx(float x) {
    float r; asm("rcp.approx.f32 %0, %1;" : "=f"(r) : "f"(x)); return r;
}
__device__ __forceinline__ float lg2_approx(float x) {
    float r; asm("lg2.approx.f32 %0, %1;" : "=f"(r) : "f"(x)); return r;
}

// Build the per-bin quadratic tables into shared memory (runs on 1 thread/block;
// redundant across blocks, ~1k cycles, hidden by cross-block overlap).
//   sh[3b+0] = A = {p2, p1, p0, q2}   den(x)  = p2 x^2 + p1 x + p0
//   sh[3b+1] = B = {q1, q0, r1, r0}   numz(x) = q2 x^2 + q1 x + q0 (y_k folded)
//                                     num2(x) = -p2 x^2 + r1 x + r0 (identity)
// All scaled by 1/s^2 so lj = log(num2/den^2) exactly (2*log s folded).
__device__ void build_table(const float* __restrict__ params,
                            float4* __restrict__ sh, float* __restrict__ sbnd)
{
    float W[KBINS], H[KBINS], D[KBINS + 1];

    { // softmax(widths) * 2*TAILB
        float mx = params[0];
        #pragma unroll
        for (int i = 1; i < KBINS; i++) mx = fmaxf(mx, params[i]);
        float s = 0.f, e[KBINS];
        #pragma unroll
        for (int i = 0; i < KBINS; i++) { e[i] = expf(params[i] - mx); s += e[i]; }
        #pragma unroll
        for (int i = 0; i < KBINS; i++) W[i] = e[i] / s * (2.0f * TAILB);
    }
    { // softmax(heights) * 2*TAILB
        float mx = params[KBINS];
        #pragma unroll
        for (int i = 1; i < KBINS; i++) mx = fmaxf(mx, params[KBINS + i]);
        float s = 0.f, e[KBINS];
        #pragma unroll
        for (int i = 0; i < KBINS; i++) { e[i] = expf(params[KBINS + i] - mx); s += e[i]; }
        #pragma unroll
        for (int i = 0; i < KBINS; i++) H[i] = e[i] / s * (2.0f * TAILB);
    }
    #pragma unroll
    for (int i = 0; i < KBINS + 1; i++) { // softplus + 1e-5
        float v = params[2 * KBINS + i];
        D[i] = log1pf(expf(-fabsf(v))) + fmaxf(v, 0.0f) + 1e-5f;
    }

    float cw[KBINS + 1], ch[KBINS + 1];
    cw[0] = -TAILB; ch[0] = -TAILB;
    float aw = 0.f, ah = 0.f;
    #pragma unroll
    for (int i = 0; i < KBINS; i++) {
        aw += W[i]; cw[i + 1] = aw - TAILB;
        ah += H[i]; ch[i + 1] = ah - TAILB;
    }

    #pragma unroll
    for (int bi = 0; bi < KBINS; bi++) {
        float xk  = cw[bi];
        float yk  = ch[bi];
        float dy  = ch[bi + 1] - ch[bi];
        float dk  = D[bi], dk1 = D[bi + 1];
        float s   = H[bi] / W[bi];
        float c   = dk + dk1 - 2.0f * s;
        float sd  = s - dk;
        float a  = 1.0f / (cw[bi + 1] - cw[bi] + 1e-8f);
        float b_ = -a * xk;

        float p2 = -c * a * a;
        float p1 = c * a * (1.0f - 2.0f * b_);
        float p0 = s + c * (b_ - b_ * b_);
        float q2 = dy * sd * a * a + yk * p2;
        float q1 = dy * a * (2.0f * b_ * sd + dk) + yk * p1;
        float q0 = dy * (sd * b_ * b_ + dk * b_) + yk * p0;
        float r1 = 2.0f * a * (c * b_ + sd);
        float r0 = c * b_ * b_ + 2.0f * sd * b_ + dk;

        float is2 = 1.0f / (s * s);
        sh[3 * bi + 0] = make_float4(p2 * is2, p1 * is2, p0 * is2, q2 * is2);
        sh[3 * bi + 1] = make_float4(q1 * is2, q0 * is2, r1 * is2, r0 * is2);
        sh[3 * bi + 2] = make_float4(0.f, 0.f, 0.f, 0.f);  // pad (bank spread)
    }
    #pragma unroll
    for (int i = 0; i < 4; i++) sbnd[i] = cw[i + 1];
}

__device__ __forceinline__ void rqs_one(
    float x, float b0, float b1, float b2, float b3,
    const float4* __restrict__ sh, float& zo, float& lo)
{
    bool inside = fabsf(x) <= TAILB;
    float xs = inside ? x : 0.0f;
    int off = ((xs > b0) + (xs > b1) + (xs > b2) + (xs > b3)) * 3;

    float4 A = sh[off];
    float4 B = sh[off + 1];

    float den  = fmaf(fmaf(A.x, xs, A.y), xs, A.z);
    float numz = fmaf(fmaf(A.w, xs, B.x), xs, B.y);
    float num2 = fmaf(fmaf(-A.x, xs, B.z), xs, B.w);

    float rA = rcp_approx(den);
    float z  = numz * rA;                    // y_k folded in

    float larg = (num2 * rA) * rA;           // s^2 scaling folded in table
    float lj   = 0.69314718056f * lg2_approx(larg);

    zo = inside ? z : x;
    lo = inside ? lj : 0.0f;
}

__global__ void __launch_bounds__(TPB, 8)
rqs_fused_kernel(const float* __restrict__ x, const float* __restrict__ params,
                 float* __restrict__ out, int n4)
{
    __shared__ float4 sh[3 * KBINS];
    __shared__ float  sbnd[4];

    int tid = threadIdx.x;
    if (tid == 0) build_table(params, sh, sbnd);
    __syncthreads();

    float b0 = sbnd[0], b1 = sbnd[1], b2 = sbnd[2], b3 = sbnd[3];

    const float4* __restrict__ x4 = (const float4*)x;
    float4* __restrict__ z4 = (float4*)out;
    float4* __restrict__ l4 = (float4*)(out + ((size_t)n4 * 4));

    int base = blockIdx.x * (TPB * VPT) + tid;

    #pragma unroll
    for (int k = 0; k < VPT; k++) {
        int i = base + k * TPB;
        if (i < n4) {
            float4 xv = __ldcs(&x4[i]);
            float4 zv, lv;
            rqs_one(xv.x, b0, b1, b2, b3, sh, zv.x, lv.x);
            rqs_one(xv.y, b0, b1, b2, b3, sh, zv.y, lv.y);
            rqs_one(xv.z, b0, b1, b2, b3, sh, zv.z, lv.z);
            rqs_one(xv.w, b0, b1, b2, b3, sh, zv.w, lv.w);
            __stcs(&z4[i], zv);
            __stcs(&l4[i], lv);
        }
    }
}

extern "C" void kernel_launch(void* const* d_in, const int* in_sizes, int n_in,
                              void* d_out, int out_size)
{
    const float* x      = (const float*)d_in[0];
    const float* params = (const float*)d_in[1];
    float* out          = (float*)d_out;

    int n  = in_sizes[0];     // 16777216
    int n4 = n >> 2;          // float4 count

    int blocks = (n4 + TPB * VPT - 1) / (TPB * VPT);
    rqs_fused_kernel<<<blocks, TPB>>>(x, params, out, n4);
}

// round 7
// speedup vs baseline: 1.1312x; 1.1312x over previous
#include <cuda_runtime.h>
#include <cuda_bf16.h>
#include <math.h>

#define KBINS 5
#define TAILB 2.5f
#define TPB 256
#define NBLK 1184   // 148 SMs * 8 resident CTAs -> one persistent wave

__device__ __forceinline__ float rcp_approx(float x) {
    float r; asm("rcp.approx.f32 %0, %1;" : "=f"(r) : "f"(x)); return r;
}
__device__ __forceinline__ float lg2_approx(float x) {
    float r; asm("lg2.approx.f32 %0, %1;" : "=f"(r) : "f"(x)); return r;
}

// Build the per-bin quadratic tables into shared memory (thread 0 of each
// persistent block; paid once per resident CTA, fully overlapped across CTAs).
//   sh[3b+0] = A = {p2, p1, p0, q2}   den(x)  = p2 x^2 + p1 x + p0
//   sh[3b+1] = B = {q1, q0, r1, r0}   numz(x) = q2 x^2 + q1 x + q0 (y_k folded)
//                                     num2(x) = -p2 x^2 + r1 x + r0 (identity)
// All scaled by 1/s^2 so lj = log(num2/den^2) exactly (2*log s folded).
__device__ void build_table(const float* __restrict__ params,
                            float4* __restrict__ sh, float* __restrict__ sbnd)
{
    float W[KBINS], H[KBINS], D[KBINS + 1];

    { // softmax(widths) * 2*TAILB
        float mx = params[0];
        #pragma unroll
        for (int i = 1; i < KBINS; i++) mx = fmaxf(mx, params[i]);
        float s = 0.f, e[KBINS];
        #pragma unroll
        for (int i = 0; i < KBINS; i++) { e[i] = expf(params[i] - mx); s += e[i]; }
        #pragma unroll
        for (int i = 0; i < KBINS; i++) W[i] = e[i] / s * (2.0f * TAILB);
    }
    { // softmax(heights) * 2*TAILB
        float mx = params[KBINS];
        #pragma unroll
        for (int i = 1; i < KBINS; i++) mx = fmaxf(mx, params[KBINS + i]);
        float s = 0.f, e[KBINS];
        #pragma unroll
        for (int i = 0; i < KBINS; i++) { e[i] = expf(params[KBINS + i] - mx); s += e[i]; }
        #pragma unroll
        for (int i = 0; i < KBINS; i++) H[i] = e[i] / s * (2.0f * TAILB);
    }
    #pragma unroll
    for (int i = 0; i < KBINS + 1; i++) { // softplus + 1e-5
        float v = params[2 * KBINS + i];
        D[i] = log1pf(expf(-fabsf(v))) + fmaxf(v, 0.0f) + 1e-5f;
    }

    float cw[KBINS + 1], ch[KBINS + 1];
    cw[0] = -TAILB; ch[0] = -TAILB;
    float aw = 0.f, ah = 0.f;
    #pragma unroll
    for (int i = 0; i < KBINS; i++) {
        aw += W[i]; cw[i + 1] = aw - TAILB;
        ah += H[i]; ch[i + 1] = ah - TAILB;
    }

    #pragma unroll
    for (int bi = 0; bi < KBINS; bi++) {
        float xk  = cw[bi];
        float yk  = ch[bi];
        float dy  = ch[bi + 1] - ch[bi];
        float dk  = D[bi], dk1 = D[bi + 1];
        float s   = H[bi] / W[bi];
        float c   = dk + dk1 - 2.0f * s;
        float sd  = s - dk;
        float a  = 1.0f / (cw[bi + 1] - cw[bi] + 1e-8f);
        float b_ = -a * xk;

        float p2 = -c * a * a;
        float p1 = c * a * (1.0f - 2.0f * b_);
        float p0 = s + c * (b_ - b_ * b_);
        float q2 = dy * sd * a * a + yk * p2;
        float q1 = dy * a * (2.0f * b_ * sd + dk) + yk * p1;
        float q0 = dy * (sd * b_ * b_ + dk * b_) + yk * p0;
        float r1 = 2.0f * a * (c * b_ + sd);
        float r0 = c * b_ * b_ + 2.0f * sd * b_ + dk;

        float is2 = 1.0f / (s * s);
        sh[3 * bi + 0] = make_float4(p2 * is2, p1 * is2, p0 * is2, q2 * is2);
        sh[3 * bi + 1] = make_float4(q1 * is2, q0 * is2, r1 * is2, r0 * is2);
        sh[3 * bi + 2] = make_float4(0.f, 0.f, 0.f, 0.f);  // pad (bank spread)
    }
    #pragma unroll
    for (int i = 0; i < 4; i++) sbnd[i] = cw[i + 1];
}

__device__ __forceinline__ void rqs_one(
    float x, float b0, float b1, float b2, float b3,
    const float4* __restrict__ sh, float& zo, float& lo)
{
    bool inside = fabsf(x) <= TAILB;
    float xs = inside ? x : 0.0f;
    int off = ((xs > b0) + (xs > b1) + (xs > b2) + (xs > b3)) * 3;

    float4 A = sh[off];
    float4 B = sh[off + 1];

    float den  = fmaf(fmaf(A.x, xs, A.y), xs, A.z);
    float numz = fmaf(fmaf(A.w, xs, B.x), xs, B.y);
    float num2 = fmaf(fmaf(-A.x, xs, B.z), xs, B.w);

    float rA = rcp_approx(den);
    float z  = numz * rA;                    // y_k folded in

    float larg = (num2 * rA) * rA;           // s^2 scaling folded in table
    float lj   = 0.69314718056f * lg2_approx(larg);

    zo = inside ? z : x;
    lo = inside ? lj : 0.0f;
}

__global__ void __launch_bounds__(TPB, 8)
rqs_persistent_kernel(const float* __restrict__ x, const float* __restrict__ params,
                      float* __restrict__ out, int n4)
{
    __shared__ float4 sh[3 * KBINS];
    __shared__ float  sbnd[4];

    int tid = threadIdx.x;
    if (tid == 0) build_table(params, sh, sbnd);
    __syncthreads();

    float b0 = sbnd[0], b1 = sbnd[1], b2 = sbnd[2], b3 = sbnd[3];

    const float4* __restrict__ x4 = (const float4*)x;
    float4* __restrict__ z4 = (float4*)out;
    float4* __restrict__ l4 = (float4*)(out + ((size_t)n4 * 4));

    int stride = NBLK * TPB;
    int i = blockIdx.x * TPB + tid;

    // Main loop, unrolled x2 with batched loads (MLP_p1 = 2)
    for (; i + stride < n4; i += 2 * stride) {
        float4 xa = x4[i];
        float4 xb = x4[i + stride];

        float4 za, la, zb, lb;
        rqs_one(xa.x, b0, b1, b2, b3, sh, za.x, la.x);
        rqs_one(xa.y, b0, b1, b2, b3, sh, za.y, la.y);
        rqs_one(xa.z, b0, b1, b2, b3, sh, za.z, la.z);
        rqs_one(xa.w, b0, b1, b2, b3, sh, za.w, la.w);
        rqs_one(xb.x, b0, b1, b2, b3, sh, zb.x, lb.x);
        rqs_one(xb.y, b0, b1, b2, b3, sh, zb.y, lb.y);
        rqs_one(xb.z, b0, b1, b2, b3, sh, zb.z, lb.z);
        rqs_one(xb.w, b0, b1, b2, b3, sh, zb.w, lb.w);

        z4[i] = za;
        l4[i] = la;
        z4[i + stride] = zb;
        l4[i + stride] = lb;
    }
    // Tail
    for (; i < n4; i += stride) {
        float4 xv = x4[i];
        float4 zv, lv;
        rqs_one(xv.x, b0, b1, b2, b3, sh, zv.x, lv.x);
        rqs_one(xv.y, b0, b1, b2, b3, sh, zv.y, lv.y);
        rqs_one(xv.z, b0, b1, b2, b3, sh, zv.z, lv.z);
        rqs_one(xv.w, b0, b1, b2, b3, sh, zv.w, lv.w);
        z4[i] = zv;
        l4[i] = lv;
    }
}

extern "C" void kernel_launch(void* const* d_in, const int* in_sizes, int n_in,
                              void* d_out, int out_size)
{
    const float* x      = (const float*)d_in[0];
    const float* params = (const float*)d_in[1];
    float* out          = (float*)d_out;

    int n  = in_sizes[0];     // 16777216
    int n4 = n >> 2;          // float4 count

    rqs_persistent_kernel<<<NBLK, TPB>>>(x, params, out, n4);
}

// round 8
// speedup vs baseline: 1.2715x; 1.1240x over previous
#include <cuda_runtime.h>
#include <cuda_bf16.h>
#include <math.h>

#define KBINS 5
#define NBINS 7     // tail bin 0, 5 real bins, tail bin 6
#define TAILB 2.5f
#define TPB 256
#define VPT 2       // float4 per thread

__device__ __forceinline__ float rcp_approx(float x) {
    float r; asm("rcp.approx.f32 %0, %1;" : "=f"(r) : "f"(x)); return r;
}
__device__ __forceinline__ float lg2_approx(float x) {
    float r; asm("lg2.approx.f32 %0, %1;" : "=f"(r) : "f"(x)); return r;
}

// Per-bin table (3 float4 stride = 48B -> bins hit distinct banks):
//   sh[3b+0] = A = {p2, p1, p0, q2}   den(x)  = p2 x^2 + p1 x + p0
//   sh[3b+1] = B = {q1, q0, r1, r0}   numz(x) = q2 x^2 + q1 x + q0 (y_k folded)
//                                     num2(x) = -p2 x^2 + r1 x + r0 (identity)
// Interior bins scaled by 1/s^2 so lj = log(num2/den^2) exactly.
// Tail bins (0,6): den=1, numz=x, num2=1 -> z=x, lj=0 exactly.

__device__ __forceinline__ void rqs_one(
    float x, float b0, float b1, float b2, float b3,
    const float4* __restrict__ sh, float& zo, float& lo)
{
    int idx = (x >= -TAILB) + (x > b0) + (x > b1) + (x > b2) + (x > b3) + (x > TAILB);
    int off = idx * 3;

    float4 A = sh[off];
    float4 B = sh[off + 1];

    float den  = fmaf(fmaf(A.x, x, A.y), x, A.z);
    float numz = fmaf(fmaf(A.w, x, B.x), x, B.y);
    float num2 = fmaf(fmaf(-A.x, x, B.z), x, B.w);

    float rA = rcp_approx(den);
    zo = numz * rA;                           // y_k folded in; tail: x*1

    float larg = (num2 * rA) * rA;            // s^2 folded in table; tail: 1
    lo = 0.69314718056f * lg2_approx(larg);   // tail: 0
}

__global__ void __launch_bounds__(TPB, 8)
rqs_fused_kernel(const float* __restrict__ x, const float* __restrict__ params,
                 float* __restrict__ out, int n4)
{
    __shared__ float4 sh[3 * NBINS];
    __shared__ float  sbnd[4];
    __shared__ float  sew[KBINS], seh[KBINS], sD[KBINS + 1];
    __shared__ float  scw[KBINS + 1], sch[KBINS + 1];

    int tid = threadIdx.x;
    int base = blockIdx.x * (TPB * VPT) + tid;

    const float4* __restrict__ x4 = (const float4*)x;
    float4* __restrict__ z4 = (float4*)out;
    float4* __restrict__ l4 = (float4*)(out + ((size_t)n4 * 4));

    // Issue x loads FIRST so their DRAM latency overlaps the table build.
    bool va = (base < n4), vb = (base + TPB < n4);
    float4 xa, xb;
    if (va) xa = x4[base];
    if (vb) xb = x4[base + TPB];

    // ---- fused table build, warp 0, parallel over lanes, fast-math ----
    if (tid < 32) {
        if (tid < KBINS) {
            sew[tid] = __expf(params[tid]);
            seh[tid] = __expf(params[KBINS + tid]);
        }
        if (tid < KBINS + 1) {
            float v = params[2 * KBINS + tid];
            sD[tid] = __logf(1.0f + __expf(-fabsf(v))) + fmaxf(v, 0.0f) + 1e-5f;
        }
        __syncwarp();
        if (tid == 0) {
            float sw = 0.f, shh = 0.f;
            #pragma unroll
            for (int i = 0; i < KBINS; i++) { sw += sew[i]; shh += seh[i]; }
            float iw = __fdividef(2.0f * TAILB, sw);
            float ih = __fdividef(2.0f * TAILB, shh);
            float aw = -TAILB, ah = -TAILB;
            scw[0] = -TAILB; sch[0] = -TAILB;
            #pragma unroll
            for (int i = 0; i < KBINS; i++) {
                aw = fmaf(sew[i], iw, aw); scw[i + 1] = aw;
                ah = fmaf(seh[i], ih, ah); sch[i + 1] = ah;
            }
        }
        __syncwarp();
        if (tid < KBINS) {
            int bi = tid;
            float xk = scw[bi], yk = sch[bi];
            float Wb = scw[bi + 1] - xk;
            float dy = sch[bi + 1] - yk;
            float dk = sD[bi], dk1 = sD[bi + 1];
            float s  = __fdividef(dy, Wb);
            float c  = dk + dk1 - 2.0f * s;
            float sd = s - dk;
            float a  = __fdividef(1.0f, Wb + 1e-8f);
            float b_ = -a * xk;

            float p2 = -c * a * a;
            float p1 = c * a * (1.0f - 2.0f * b_);
            float p0 = s + c * (b_ - b_ * b_);
            float q2 = dy * sd * a * a + yk * p2;
            float q1 = dy * a * (2.0f * b_ * sd + dk) + yk * p1;
            float q0 = dy * (sd * b_ * b_ + dk * b_) + yk * p0;
            float r1 = 2.0f * a * (c * b_ + sd);
            float r0 = c * b_ * b_ + 2.0f * sd * b_ + dk;

            float is2 = __fdividef(1.0f, s * s);
            sh[3 * (bi + 1) + 0] = make_float4(p2 * is2, p1 * is2, p0 * is2, q2 * is2);
            sh[3 * (bi + 1) + 1] = make_float4(q1 * is2, q0 * is2, r1 * is2, r0 * is2);
        } else if (tid < KBINS + 2) {
            // tail bins 0 and 6: den=1, numz=x, num2=1
            int bb = (tid == KBINS) ? 0 : (NBINS - 1);
            sh[3 * bb + 0] = make_float4(0.f, 0.f, 1.f, 0.f);
            sh[3 * bb + 1] = make_float4(1.f, 0.f, 0.f, 1.f);
        }
        __syncwarp();
        if (tid < 4) sbnd[tid] = scw[tid + 1];
    }
    __syncthreads();
    // -------------------------------------------------------------------

    float b0 = sbnd[0], b1 = sbnd[1], b2 = sbnd[2], b3 = sbnd[3];

    if (va) {
        float4 zv, lv;
        rqs_one(xa.x, b0, b1, b2, b3, sh, zv.x, lv.x);
        rqs_one(xa.y, b0, b1, b2, b3, sh, zv.y, lv.y);
        rqs_one(xa.z, b0, b1, b2, b3, sh, zv.z, lv.z);
        rqs_one(xa.w, b0, b1, b2, b3, sh, zv.w, lv.w);
        z4[base] = zv;
        l4[base] = lv;
    }
    if (vb) {
        float4 zv, lv;
        rqs_one(xb.x, b0, b1, b2, b3, sh, zv.x, lv.x);
        rqs_one(xb.y, b0, b1, b2, b3, sh, zv.y, lv.y);
        rqs_one(xb.z, b0, b1, b2, b3, sh, zv.z, lv.z);
        rqs_one(xb.w, b0, b1, b2, b3, sh, zv.w, lv.w);
        z4[base + TPB] = zv;
        l4[base + TPB] = lv;
    }
}

extern "C" void kernel_launch(void* const* d_in, const int* in_sizes, int n_in,
                              void* d_out, int out_size)
{
    const float* x      = (const float*)d_in[0];
    const float* params = (const float*)d_in[1];
    float* out          = (float*)d_out;

    int n  = in_sizes[0];     // 16777216
    int n4 = n >> 2;          // float4 count

    int blocks = (n4 + TPB * VPT - 1) / (TPB * VPT);
    rqs_fused_kernel<<<blocks, TPB>>>(x, params, out, n4);
}